// round 17
// baseline (speedup 1.0000x reference)
#include <cuda_runtime.h>
#include <stdint.h>
#include <math.h>

// Problem constants
#define BB 8
#define NS 1024
#define CC 384
#define HH 6
#define DD 64
#define SPAN 384
#define TWOSPAN 768

// ---------------- device scratch ----------------
__device__ float g_q[BB * NS * CC];
__device__ float g_k[BB * NS * CC];
__device__ float g_v[BB * NS * CC];
__device__ float g_att[BB * NS * CC];
__device__ float g_posk[TWOSPAN * CC];
__device__ float g_posq[TWOSPAN * CC];
__device__ float g_Qp[(size_t)BB * HH * NS * TWOSPAN];
__device__ float g_Kp[(size_t)BB * HH * NS * TWOSPAN];

// ---------------- tf32 helpers ----------------
__device__ __forceinline__ uint32_t f2tf(float x) {
    uint32_t r;
    asm("cvt.rna.tf32.f32 %0, %1;" : "=r"(r) : "f"(x));
    return r;
}

// D = A(16x8,row) * B(8x8,col) + D, tf32 inputs, f32 accum
__device__ __forceinline__ void mma8(float* c, const uint32_t* a, const uint32_t* b) {
    asm volatile(
        "mma.sync.aligned.m16n8k8.row.col.f32.tf32.tf32.f32 "
        "{%0,%1,%2,%3},{%4,%5,%6,%7},{%8,%9},{%0,%1,%2,%3};"
        : "+f"(c[0]), "+f"(c[1]), "+f"(c[2]), "+f"(c[3])
        : "r"(a[0]), "r"(a[1]), "r"(a[2]), "r"(a[3]), "r"(b[0]), "r"(b[1]));
}

// ---------------- projection GEMM (MMA): C = A(Mx384) @ W(384x384) + bias ----------------
__global__ void __launch_bounds__(256) proj_mma(
    const float* __restrict__ A, int M,
    const float* __restrict__ W0, const float* __restrict__ W1, const float* __restrict__ W2,
    const float* __restrict__ B0, const float* __restrict__ B1, const float* __restrict__ B2,
    float* __restrict__ C0, float* __restrict__ C1, float* __restrict__ C2)
{
    const float* W    = blockIdx.z == 0 ? W0 : (blockIdx.z == 1 ? W1 : W2);
    const float* bias = blockIdx.z == 0 ? B0 : (blockIdx.z == 1 ? B1 : B2);
    float*       C    = blockIdx.z == 0 ? C0 : (blockIdx.z == 1 ? C1 : C2);

    __shared__ uint32_t aS[128][36];
    __shared__ uint32_t wS[32][72];

    int tid = threadIdx.x, w = tid >> 5, lane = tid & 31, g = lane >> 2, tg = lane & 3;
    int wm = w >> 1, wn = w & 1;
    int m0 = blockIdx.y * 128, n0 = blockIdx.x * 64;

    float c[2][4][4];
#pragma unroll
    for (int mt = 0; mt < 2; mt++)
#pragma unroll
        for (int nt = 0; nt < 4; nt++)
#pragma unroll
            for (int r = 0; r < 4; r++) c[mt][nt][r] = 0.f;

    int ar = tid >> 1, ac = (tid & 1) << 4;
    int wr = tid >> 3, wc = (tid & 7) << 3;

    for (int k0 = 0; k0 < 384; k0 += 32) {
        const float* ap = A + (size_t)(m0 + ar) * 384 + k0 + ac;
#pragma unroll
        for (int t = 0; t < 4; t++) {
            float4 v4 = *(const float4*)(ap + t * 4);
            aS[ar][ac + t * 4 + 0] = f2tf(v4.x);
            aS[ar][ac + t * 4 + 1] = f2tf(v4.y);
            aS[ar][ac + t * 4 + 2] = f2tf(v4.z);
            aS[ar][ac + t * 4 + 3] = f2tf(v4.w);
        }
        const float* wp = W + (size_t)(k0 + wr) * 384 + n0 + wc;
#pragma unroll
        for (int t = 0; t < 2; t++) {
            float4 v4 = *(const float4*)(wp + t * 4);
            wS[wr][wc + t * 4 + 0] = f2tf(v4.x);
            wS[wr][wc + t * 4 + 1] = f2tf(v4.y);
            wS[wr][wc + t * 4 + 2] = f2tf(v4.z);
            wS[wr][wc + t * 4 + 3] = f2tf(v4.w);
        }
        __syncthreads();

#pragma unroll
        for (int ks = 0; ks < 4; ks++) {
            uint32_t bf[4][2];
#pragma unroll
            for (int nt = 0; nt < 4; nt++) {
                bf[nt][0] = wS[8 * ks + tg][32 * wn + 8 * nt + g];
                bf[nt][1] = wS[8 * ks + tg + 4][32 * wn + 8 * nt + g];
            }
#pragma unroll
            for (int mt = 0; mt < 2; mt++) {
                int r = 32 * wm + 16 * mt + g;
                uint32_t af[4];
                af[0] = aS[r][8 * ks + tg];
                af[1] = aS[r + 8][8 * ks + tg];
                af[2] = aS[r][8 * ks + tg + 4];
                af[3] = aS[r + 8][8 * ks + tg + 4];
#pragma unroll
                for (int nt = 0; nt < 4; nt++) mma8(c[mt][nt], af, bf[nt]);
            }
        }
        __syncthreads();
    }

#pragma unroll
    for (int mt = 0; mt < 2; mt++)
#pragma unroll
        for (int nt = 0; nt < 4; nt++) {
            int row = m0 + 32 * wm + 16 * mt + g;
            int col = n0 + 32 * wn + 8 * nt + 2 * tg;
            float bx = bias[col], by = bias[col + 1];
            float2 o1 = {c[mt][nt][0] + bx, c[mt][nt][1] + by};
            float2 o2 = {c[mt][nt][2] + bx, c[mt][nt][3] + by};
            *(float2*)(C + (size_t)row * 384 + col) = o1;
            *(float2*)(C + (size_t)(row + 8) * 384 + col) = o2;
        }
}

// ---------------- Qp/Kp batched NT GEMM (MMA), K=64 one-shot ----------------
__global__ void __launch_bounds__(256) qpkp_mma()
{
    extern __shared__ uint32_t sm_u[];
    uint32_t (*aS)[68] = (uint32_t(*)[68])sm_u;
    uint32_t (*bS)[68] = (uint32_t(*)[68])(sm_u + 128 * 68);

    int z = blockIdx.z, which = z & 1, bh = z >> 1;
    int b = bh / HH, h = bh % HH;
    const float* Ab = (which ? g_k : g_q) + (size_t)b * NS * CC + h * DD;
    const float* Pb = (which ? g_posq : g_posk) + h * DD;
    float* Out = (which ? g_Kp : g_Qp) + (size_t)bh * NS * TWOSPAN;
    int i0 = blockIdx.y * 128, p0 = blockIdx.x * 128;

    int tid = threadIdx.x, w = tid >> 5, lane = tid & 31, g = lane >> 2, tg = lane & 3;
    int wm = w >> 2, wn = w & 3;

    int r = tid >> 1, cb = (tid & 1) * 32;
#pragma unroll
    for (int t = 0; t < 8; t++) {
        float4 v4 = *(const float4*)(Ab + (size_t)(i0 + r) * CC + cb + t * 4);
        aS[r][cb + t * 4 + 0] = f2tf(v4.x);
        aS[r][cb + t * 4 + 1] = f2tf(v4.y);
        aS[r][cb + t * 4 + 2] = f2tf(v4.z);
        aS[r][cb + t * 4 + 3] = f2tf(v4.w);
        float4 u4 = *(const float4*)(Pb + (size_t)(p0 + r) * CC + cb + t * 4);
        bS[r][cb + t * 4 + 0] = f2tf(u4.x);
        bS[r][cb + t * 4 + 1] = f2tf(u4.y);
        bS[r][cb + t * 4 + 2] = f2tf(u4.z);
        bS[r][cb + t * 4 + 3] = f2tf(u4.w);
    }
    __syncthreads();

    float c[4][4][4];
#pragma unroll
    for (int mt = 0; mt < 4; mt++)
#pragma unroll
        for (int nt = 0; nt < 4; nt++)
#pragma unroll
            for (int q = 0; q < 4; q++) c[mt][nt][q] = 0.f;

#pragma unroll
    for (int ks = 0; ks < 8; ks++) {
        uint32_t bf[4][2], af[4][4];
#pragma unroll
        for (int nt = 0; nt < 4; nt++) {
            int pr = 32 * wn + 8 * nt + g;
            bf[nt][0] = bS[pr][8 * ks + tg];
            bf[nt][1] = bS[pr][8 * ks + tg + 4];
        }
#pragma unroll
        for (int mt = 0; mt < 4; mt++) {
            int rr = 64 * wm + 16 * mt + g;
            af[mt][0] = aS[rr][8 * ks + tg];
            af[mt][1] = aS[rr + 8][8 * ks + tg];
            af[mt][2] = aS[rr][8 * ks + tg + 4];
            af[mt][3] = aS[rr + 8][8 * ks + tg + 4];
        }
#pragma unroll
        for (int mt = 0; mt < 4; mt++)
#pragma unroll
            for (int nt = 0; nt < 4; nt++) mma8(c[mt][nt], af[mt], bf[nt]);
    }

#pragma unroll
    for (int mt = 0; mt < 4; mt++)
#pragma unroll
        for (int nt = 0; nt < 4; nt++) {
            int row = i0 + 64 * wm + 16 * mt + g;
            int col = p0 + 32 * wn + 8 * nt + 2 * tg;
            float2 o1 = {c[mt][nt][0], c[mt][nt][1]};
            float2 o2 = {c[mt][nt][2], c[mt][nt][3]};
            *(float2*)(Out + (size_t)row * TWOSPAN + col) = o1;
            *(float2*)(Out + (size_t)(row + 8) * TWOSPAN + col) = o2;
        }
}

// ---------------- fused flash attention (MMA) with SMEM-staged positional bands ----------------
// Block: 128 q-rows, 8 warps x 16 rows each, K/V tiles of 64.
// QpS[il][u]  = Qp[i0+il, clamp(i0+il - j0 - u + 384)]         (128 x 64, stride 72)
// KpS[jl][t]  = Kp[j0+jl, clamp(i0+t  - j0 - jl + 384)]        (64 x 128, stride 132)
__global__ void __launch_bounds__(256) attn_mma()
{
    extern __shared__ uint32_t sm_u[];
    uint32_t (*kS)[68]  = (uint32_t(*)[68])sm_u;                                   // 64 x 68
    uint32_t (*vS)[72]  = (uint32_t(*)[72])(sm_u + 64 * 68);                       // 64 x 72
    uint32_t (*pS)[68]  = (uint32_t(*)[68])(sm_u + 64 * 68 + 64 * 72);             // 128 x 68
    float*    QpS       = (float*)(sm_u + 64 * 68 + 64 * 72 + 128 * 68);           // 128 x 72
    float*    KpS       = QpS + 128 * 72;                                           // 64 x 132

    int bh = blockIdx.y, b = bh / HH, h = bh % HH;
    int i0 = blockIdx.x * 128;
    int tid = threadIdx.x, w = tid >> 5, lane = tid & 31, g = lane >> 2, tg = lane & 3;
    int il1 = 16 * w + g, il2 = il1 + 8;
    int i1 = i0 + il1, i2 = i0 + il2;

    const float* qB = g_q + (size_t)b * NS * CC + h * DD;
    const float* kB = g_k + (size_t)b * NS * CC + h * DD;
    const float* vB = g_v + (size_t)b * NS * CC + h * DD;
    const float* QpB = g_Qp + (size_t)bh * NS * TWOSPAN;
    const float* KpB = g_Kp + (size_t)bh * NS * TWOSPAN;

    // Q fragments held in registers for the whole kernel
    uint32_t qf[8][4];
#pragma unroll
    for (int ks = 0; ks < 8; ks++) {
        qf[ks][0] = f2tf(qB[(size_t)i1 * CC + 8 * ks + tg]);
        qf[ks][1] = f2tf(qB[(size_t)i2 * CC + 8 * ks + tg]);
        qf[ks][2] = f2tf(qB[(size_t)i1 * CC + 8 * ks + tg + 4]);
        qf[ks][3] = f2tf(qB[(size_t)i2 * CC + 8 * ks + tg + 4]);
    }

    float o[8][4];
#pragma unroll
    for (int nt = 0; nt < 8; nt++)
#pragma unroll
        for (int q = 0; q < 4; q++) o[nt][q] = 0.f;
    float m1 = -1e30f, m2 = -1e30f, l1 = 0.f, l2 = 0.f;
    const float isc = rsqrtf((float)(DD * 3));

    int lr = tid >> 2, lc = (tid & 3) * 16;
    int pr1 = 16 * w + g, pr2 = pr1 + 8;

    for (int kt = 0; kt < NS / 64; kt++) {
        int j0 = kt * 64;

        // cooperative load of K/V tiles (tf32-converted)
#pragma unroll
        for (int t = 0; t < 4; t++) {
            float4 v4 = *(const float4*)(kB + (size_t)(j0 + lr) * CC + lc + t * 4);
            kS[lr][lc + t * 4 + 0] = f2tf(v4.x);
            kS[lr][lc + t * 4 + 1] = f2tf(v4.y);
            kS[lr][lc + t * 4 + 2] = f2tf(v4.z);
            kS[lr][lc + t * 4 + 3] = f2tf(v4.w);
            float4 u4 = *(const float4*)(vB + (size_t)(j0 + lr) * CC + lc + t * 4);
            vS[lr][lc + t * 4 + 0] = f2tf(u4.x);
            vS[lr][lc + t * 4 + 1] = f2tf(u4.y);
            vS[lr][lc + t * 4 + 2] = f2tf(u4.z);
            vS[lr][lc + t * 4 + 3] = f2tf(u4.w);
        }

        // stage positional bands, fully coalesced
#pragma unroll
        for (int e = 0; e < 32; e++) {
            int idx = tid + e * 256;          // 128*64 elements
            int il = idx >> 6, u = idx & 63;
            int p = i0 + il - j0 - u + SPAN;
            p = min(max(p, 0), TWOSPAN - 1);
            QpS[il * 72 + u] = QpB[(size_t)(i0 + il) * TWOSPAN + p];
        }
#pragma unroll
        for (int e = 0; e < 32; e++) {
            int idx = tid + e * 256;          // 64*128 elements
            int jl = idx >> 7, t = idx & 127;
            int p = i0 + t - j0 - jl + SPAN;
            p = min(max(p, 0), TWOSPAN - 1);
            KpS[jl * 132 + t] = KpB[(size_t)(j0 + jl) * TWOSPAN + p];
        }
        __syncthreads();

        // S = Q K^T
        float s[8][4];
#pragma unroll
        for (int nt = 0; nt < 8; nt++)
#pragma unroll
            for (int q = 0; q < 4; q++) s[nt][q] = 0.f;
#pragma unroll
        for (int ks = 0; ks < 8; ks++)
#pragma unroll
            for (int nt = 0; nt < 8; nt++) {
                uint32_t bf[2];
                bf[0] = kS[8 * nt + g][8 * ks + tg];
                bf[1] = kS[8 * nt + g][8 * ks + tg + 4];
                mma8(s[nt], qf[ks], bf);
            }

        // positional adds (from SMEM) + scale + row max
        float mx1 = -1e30f, mx2 = -1e30f;
#pragma unroll
        for (int nt = 0; nt < 8; nt++) {
            int jl = 8 * nt + 2 * tg;
            float2 qp1 = *(float2*)&QpS[il1 * 72 + jl];
            float2 qp2 = *(float2*)&QpS[il2 * 72 + jl];
            float ka0 = KpS[jl * 132 + il1];
            float kb0 = KpS[(jl + 1) * 132 + il1];
            float ka8 = KpS[jl * 132 + il2];
            float kb8 = KpS[(jl + 1) * 132 + il2];
            s[nt][0] = (s[nt][0] + qp1.x + ka0) * isc;
            s[nt][1] = (s[nt][1] + qp1.y + kb0) * isc;
            s[nt][2] = (s[nt][2] + qp2.x + ka8) * isc;
            s[nt][3] = (s[nt][3] + qp2.y + kb8) * isc;
            mx1 = fmaxf(mx1, fmaxf(s[nt][0], s[nt][1]));
            mx2 = fmaxf(mx2, fmaxf(s[nt][2], s[nt][3]));
        }
        mx1 = fmaxf(mx1, __shfl_xor_sync(0xffffffffu, mx1, 1));
        mx1 = fmaxf(mx1, __shfl_xor_sync(0xffffffffu, mx1, 2));
        mx2 = fmaxf(mx2, __shfl_xor_sync(0xffffffffu, mx2, 1));
        mx2 = fmaxf(mx2, __shfl_xor_sync(0xffffffffu, mx2, 2));

        // online softmax update
        float nm1 = fmaxf(m1, mx1), nm2 = fmaxf(m2, mx2);
        float f1 = __expf(m1 - nm1), f2 = __expf(m2 - nm2);
        m1 = nm1; m2 = nm2;
        float rs1 = 0.f, rs2 = 0.f;
#pragma unroll
        for (int nt = 0; nt < 8; nt++) {
            s[nt][0] = __expf(s[nt][0] - nm1);
            s[nt][1] = __expf(s[nt][1] - nm1);
            s[nt][2] = __expf(s[nt][2] - nm2);
            s[nt][3] = __expf(s[nt][3] - nm2);
            rs1 += s[nt][0] + s[nt][1];
            rs2 += s[nt][2] + s[nt][3];
        }
        rs1 += __shfl_xor_sync(0xffffffffu, rs1, 1);
        rs1 += __shfl_xor_sync(0xffffffffu, rs1, 2);
        rs2 += __shfl_xor_sync(0xffffffffu, rs2, 1);
        rs2 += __shfl_xor_sync(0xffffffffu, rs2, 2);
        l1 = l1 * f1 + rs1;
        l2 = l2 * f2 + rs2;
#pragma unroll
        for (int nt = 0; nt < 8; nt++) {
            o[nt][0] *= f1; o[nt][1] *= f1;
            o[nt][2] *= f2; o[nt][3] *= f2;
        }

        // write P to per-warp SMEM (tf32)
#pragma unroll
        for (int nt = 0; nt < 8; nt++) {
            uint2 t1 = {f2tf(s[nt][0]), f2tf(s[nt][1])};
            *(uint2*)&pS[pr1][8 * nt + 2 * tg] = t1;
            uint2 t2 = {f2tf(s[nt][2]), f2tf(s[nt][3])};
            *(uint2*)&pS[pr2][8 * nt + 2 * tg] = t2;
        }
        __syncwarp();

        // O += P V
#pragma unroll
        for (int ks = 0; ks < 8; ks++) {
            uint32_t af[4];
            af[0] = pS[pr1][8 * ks + tg];
            af[1] = pS[pr2][8 * ks + tg];
            af[2] = pS[pr1][8 * ks + tg + 4];
            af[3] = pS[pr2][8 * ks + tg + 4];
#pragma unroll
            for (int nt = 0; nt < 8; nt++) {
                uint32_t bf[2];
                bf[0] = vS[8 * ks + tg][8 * nt + g];
                bf[1] = vS[8 * ks + tg + 4][8 * nt + g];
                mma8(o[nt], af, bf);
            }
        }
        __syncthreads();
    }

    // epilogue
    float v1 = 1.0f / l1, v2 = 1.0f / l2;
    float* oB = g_att + (size_t)b * NS * CC + h * DD;
#pragma unroll
    for (int nt = 0; nt < 8; nt++) {
        int d = 8 * nt + 2 * tg;
        float2 a = {o[nt][0] * v1, o[nt][1] * v1};
        float2 bb = {o[nt][2] * v2, o[nt][3] * v2};
        *(float2*)(oB + (size_t)i1 * CC + d) = a;
        *(float2*)(oB + (size_t)i2 * CC + d) = bb;
    }
}

// ---------------- host launcher ----------------
extern "C" void kernel_launch(void* const* d_in, const int* in_sizes, int n_in,
                              void* d_out, int out_size)
{
    (void)in_sizes; (void)n_in; (void)out_size;
    const float* x   = (const float*)d_in[0];
    const float* rel = (const float*)d_in[2];
    const float* Wq  = (const float*)d_in[3];  const float* bq  = (const float*)d_in[4];
    const float* Wk  = (const float*)d_in[5];  const float* bk  = (const float*)d_in[6];
    const float* Wv  = (const float*)d_in[7];  const float* bv  = (const float*)d_in[8];
    const float* Wpk = (const float*)d_in[9];  const float* bpk = (const float*)d_in[10];
    const float* Wpq = (const float*)d_in[11]; const float* bpq = (const float*)d_in[12];
    const float* Wo  = (const float*)d_in[13]; const float* bo  = (const float*)d_in[14];
    float* out = (float*)d_out;

    float *q, *k, *v, *att, *pk, *pq;
    cudaGetSymbolAddress((void**)&q,   g_q);
    cudaGetSymbolAddress((void**)&k,   g_k);
    cudaGetSymbolAddress((void**)&v,   g_v);
    cudaGetSymbolAddress((void**)&att, g_att);
    cudaGetSymbolAddress((void**)&pk,  g_posk);
    cudaGetSymbolAddress((void**)&pq,  g_posq);

    const int QPKP_SMEM = 2 * 128 * 68 * 4;                                        // 69632
    const int ATTN_SMEM = (64 * 68 + 64 * 72 + 128 * 68 + 128 * 72 + 64 * 132) * 4; // 141312
    cudaFuncSetAttribute(qpkp_mma, cudaFuncAttributeMaxDynamicSharedMemorySize, QPKP_SMEM);
    cudaFuncSetAttribute(attn_mma, cudaFuncAttributeMaxDynamicSharedMemorySize, ATTN_SMEM);

    dim3 blk(256);
    // q,k,v projections (z-batched)
    proj_mma<<<dim3(CC / 64, (BB * NS) / 128, 3), blk>>>(
        x, BB * NS, Wq, Wk, Wv, bq, bk, bv, q, k, v);
    // pos_k, pos_q projections (z-batched)
    proj_mma<<<dim3(CC / 64, TWOSPAN / 128, 2), blk>>>(
        rel, TWOSPAN, Wpk, Wpq, nullptr, bpk, bpq, nullptr, pk, pq, nullptr);
    // Qp = q @ pos_k^T, Kp = k @ pos_q^T per (b,h)
    qpkp_mma<<<dim3(TWOSPAN / 128, NS / 128, BB * HH * 2), blk, QPKP_SMEM>>>();
    // fused attention
    attn_mma<<<dim3(NS / 128, BB * HH), blk, ATTN_SMEM>>>();
    // output projection
    proj_mma<<<dim3(CC / 64, (BB * NS) / 128, 1), blk>>>(
        att, BB * NS, Wo, nullptr, nullptr, bo, nullptr, nullptr, out, nullptr, nullptr);
}